// round 3
// baseline (speedup 1.0000x reference)
#include <cuda_runtime.h>
#include <cuda_bf16.h>

// AdaptiveTokenSelector:
//   out[0 .. B*S*512)   = top-512 values per score row, sorted descending (f32)
//   out[B*S*512 .. +BS) = k_per_query = int(256 + 256*sigmoid(Q.W + b)) as f32
//
// One CTA (512 threads) per row, 8 register keys/thread:
//   - 4x 8-bit MSD radix select; pass 0 specialized, passes 1-3 warp-early-exit
//   - warp-aggregated (__match_any_sync) histograms
//   - ballot-aggregated compaction of > threshold, pad with threshold
//   - bitonic 512 sort: double-buffered smem stages (1 bar each) + shfl stages
//   - fused importance gate

#define TPB      512
#define ROWLEN   4096
#define KSEL     512

__device__ __forceinline__ unsigned f2k(float f) {
    unsigned u = __float_as_uint(f);
    return u ^ ((unsigned)((int)u >> 31) | 0x80000000u);
}

__device__ __forceinline__ float k2f(unsigned k) {
    unsigned u = (k & 0x80000000u) ? (k ^ 0x80000000u) : ~k;
    return __uint_as_float(u);
}

// find the crossing bin in bins[256] for remaining count kr; update sh_prefix/sh_kr
__device__ __forceinline__ void select_bin(volatile unsigned* bins, int t, int shift,
                                           unsigned prefix, unsigned kr,
                                           unsigned* sh_prefix, unsigned* sh_kr) {
    // lane t owns bins [8t, 8t+8); suffix-scan across lanes via shfl
    unsigned c[8], partial = 0;
    #pragma unroll
    for (int i = 0; i < 8; i++) { c[i] = bins[t * 8 + i]; partial += c[i]; }
    unsigned s = partial;
    #pragma unroll
    for (int off = 1; off < 32; off <<= 1) {
        unsigned v = __shfl_down_sync(0xFFFFFFFFu, s, off);
        if (t + off < 32) s += v;
    }
    unsigned cum = s - partial;      // matching keys in all higher bins
    #pragma unroll
    for (int i = 7; i >= 0; i--) {
        unsigned nc = cum + c[i];
        if (cum < kr && nc >= kr) {  // crossing bin: unique globally
            *sh_prefix = prefix | ((unsigned)(t * 8 + i) << shift);
            *sh_kr = kr - cum;
        }
        cum = nc;
    }
}

__global__ __launch_bounds__(TPB) void topk_kernel(const float* __restrict__ scores,
                                                   const float* __restrict__ Q,
                                                   const float* __restrict__ W,
                                                   const float* __restrict__ bias,
                                                   float* __restrict__ out,
                                                   float* __restrict__ outk,
                                                   int D) {
    __shared__ unsigned bins[256];
    __shared__ unsigned skeys[2][KSEL];    // ping-pong for bitonic
    __shared__ float red[TPB / 32];
    __shared__ unsigned sh_prefix, sh_kr, sh_cnt;

    const int t = threadIdx.x;
    const unsigned lane = t & 31;
    const int wid = t >> 5;
    const long long row = blockIdx.x;
    const float4* src = (const float4*)(scores + row * (long long)ROWLEN);

    // ---- load 8 floats/thread, convert to sortable keys ----
    unsigned keys[8];
    {
        float4 a = src[t];
        float4 b = src[t + TPB];
        keys[0] = f2k(a.x); keys[1] = f2k(a.y); keys[2] = f2k(a.z); keys[3] = f2k(a.w);
        keys[4] = f2k(b.x); keys[5] = f2k(b.y); keys[6] = f2k(b.z); keys[7] = f2k(b.w);
    }

    // ---- fused importance gate: partial dot Q_row . W ----
    if (outk) {
        const float2* q2 = (const float2*)(Q + row * (long long)D);
        const float2* w2 = (const float2*)W;
        float s = 0.0f;
        for (int i = t; i < (D >> 1); i += TPB) {
            float2 q = q2[i], w = w2[i];
            s += q.x * w.x + q.y * w.y;
        }
        #pragma unroll
        for (int off = 16; off; off >>= 1) s += __shfl_down_sync(0xFFFFFFFFu, s, off);
        if (lane == 0) red[wid] = s;
    }

    if (t == 0) { sh_prefix = 0; sh_kr = KSEL; sh_cnt = 0; }
    if (t < 256) bins[t] = 0;
    __syncthreads();

    // ---- pass 0 (specialized: every key is a candidate) ----
    #pragma unroll
    for (int i = 0; i < 8; i++) {
        unsigned bin = keys[i] >> 24;
        unsigned grp = __match_any_sync(0xFFFFFFFFu, bin);
        if (lane == (unsigned)(__ffs(grp) - 1))
            atomicAdd(&bins[bin], (unsigned)__popc(grp));
    }
    __syncthreads();

    if (outk && t == 0) {   // finish the gate while bins settle
        float s = bias[0];
        #pragma unroll
        for (int w = 0; w < TPB / 32; w++) s += red[w];
        float imp = 1.0f / (1.0f + expf(-s));
        outk[row] = (float)(int)(256.0f + 256.0f * imp);
    }
    if (t < 32) select_bin(bins, t, 24, 0u, KSEL, &sh_prefix, &sh_kr);
    __syncthreads();

    // ---- passes 1..3 with warp early-exit ----
    unsigned mask = 0xFF000000u;
    #pragma unroll 1
    for (int pass = 1; pass < 4; pass++) {
        const int shift = 24 - 8 * pass;
        if (t < 256) bins[t] = 0;
        __syncthreads();

        const unsigned prefix = sh_prefix;
        const unsigned kr     = sh_kr;

        unsigned cf = 0;   // candidate flags for my 8 keys
        #pragma unroll
        for (int i = 0; i < 8; i++)
            cf |= ((keys[i] & mask) == prefix) ? (1u << i) : 0u;

        if (__ballot_sync(0xFFFFFFFFu, cf != 0)) {   // warp has candidates
            #pragma unroll
            for (int i = 0; i < 8; i++) {
                bool c = (cf >> i) & 1;
                unsigned bin = c ? ((keys[i] >> shift) & 0xFF) : 0xFFFFFFFFu;
                unsigned grp = __match_any_sync(0xFFFFFFFFu, bin);
                if (c && lane == (unsigned)(__ffs(grp) - 1))
                    atomicAdd(&bins[bin], (unsigned)__popc(grp));
            }
        }
        __syncthreads();

        if (t < 32) select_bin(bins, t, shift, prefix, kr, &sh_prefix, &sh_kr);
        mask |= 0xFFu << shift;
        __syncthreads();
    }

    const unsigned T   = sh_prefix;       // exact 512th-largest key
    const unsigned kGT = KSEL - sh_kr;    // # keys strictly greater than T

    // ---- compact keys > T via ballot-aggregated atomics ----
    const unsigned lt_mask = (lane == 0) ? 0u : (0xFFFFFFFFu >> (32 - lane));
    #pragma unroll
    for (int i = 0; i < 8; i++) {
        bool p = keys[i] > T;
        unsigned bal = __ballot_sync(0xFFFFFFFFu, p);
        unsigned base = 0;
        if (lane == 0 && bal) base = atomicAdd(&sh_cnt, (unsigned)__popc(bal));
        base = __shfl_sync(0xFFFFFFFFu, base, 0);
        if (p) skeys[0][base + __popc(bal & lt_mask)] = keys[i];
    }
    __syncthreads();
    if ((unsigned)t >= kGT) skeys[0][t] = T;   // pad ties
    __syncthreads();

    // ---- hybrid bitonic sort (descending), element t in register v ----
    unsigned v = skeys[0][t];
    int buf = 0;

    // k = 2..32: pure shfl, no barriers
    #pragma unroll
    for (int k2 = 2; k2 <= 32; k2 <<= 1) {
        #pragma unroll
        for (int j = k2 >> 1; j > 0; j >>= 1) {
            unsigned o = __shfl_xor_sync(0xFFFFFFFFu, v, j);
            bool up    = ((t & k2) == 0);
            bool lower = ((t & j)  == 0);
            v = (up == lower) ? max(v, o) : min(v, o);
        }
    }
    // k = 64..512: j >= 32 via double-buffered smem (1 bar/stage), j < 32 via shfl
    #pragma unroll 1
    for (int k2 = 64; k2 <= KSEL; k2 <<= 1) {
        #pragma unroll 1
        for (int j = k2 >> 1; j >= 32; j >>= 1) {
            buf ^= 1;
            skeys[buf][t] = v;
            __syncthreads();
            unsigned o = skeys[buf][t ^ j];
            bool up    = ((t & k2) == 0);
            bool lower = ((t & j)  == 0);
            v = (up == lower) ? max(v, o) : min(v, o);
        }
        #pragma unroll
        for (int j = 16; j > 0; j >>= 1) {
            unsigned o = __shfl_xor_sync(0xFFFFFFFFu, v, j);
            bool up    = ((t & k2) == 0);
            bool lower = ((t & j)  == 0);
            v = (up == lower) ? max(v, o) : min(v, o);
        }
    }

    out[row * (long long)KSEL + t] = k2f(v);
}

extern "C" void kernel_launch(void* const* d_in, const int* in_sizes, int n_in,
                              void* d_out, int out_size) {
    const float* Q      = (const float*)d_in[0];
    const float* scores = (const float*)d_in[1];
    const float* W      = (const float*)d_in[2];
    const float* b      = (const float*)d_in[3];

    const int D = in_sizes[2];                        // 1024
    const long long BS = (long long)in_sizes[0] / D;  // B*S = 16384

    float* out  = (float*)d_out;
    float* outk = ((long long)out_size >= BS * KSEL + BS) ? out + BS * KSEL : nullptr;

    topk_kernel<<<(unsigned)BS, TPB>>>(scores, Q, W, b, out, outk, D);
}

// round 4
// speedup vs baseline: 1.4497x; 1.4497x over previous
#include <cuda_runtime.h>
#include <cuda_bf16.h>

// AdaptiveTokenSelector:
//   out[0 .. B*S*512)   = top-512 values per score row, sorted descending (f32)
//   out[B*S*512 .. +BS) = k_per_query = int(256 + 256*sigmoid(Q.W + b)) as f32
//
// One CTA (512 threads) per row, 8 register keys/thread:
//   - 12/10/10-bit MSD radix select: pass A = 4096-bin smem histogram (plain
//     atomics, low collision), passes B/C = 1024-bin over ~200 candidates
//   - crossing bin found by block suffix-scan (uint4 + shfl), not per-pass probing
//   - ballot-aggregated compaction of keys > threshold, pad with threshold
//   - bitonic 512 sort: double-buffered smem stages (1 bar) + shfl stages
//   - fused importance gate

#define TPB      512
#define ROWLEN   4096
#define KSEL     512

__device__ __forceinline__ unsigned f2k(float f) {
    unsigned u = __float_as_uint(f);
    return u ^ ((unsigned)((int)u >> 31) | 0x80000000u);
}

__device__ __forceinline__ float k2f(unsigned k) {
    unsigned u = (k & 0x80000000u) ? (k ^ 0x80000000u) : ~k;
    return __uint_as_float(u);
}

// Block-wide suffix scan over NB bins; finds the bin where the kr-th largest
// key falls (bins ascending by key value). Writes new prefix/kr. 2 barriers.
template<int NB>
__device__ __forceinline__ void scan_select(const unsigned* __restrict__ bins,
                                            unsigned* wred,
                                            int t, unsigned lane, int wid,
                                            unsigned kr, unsigned prefix_base,
                                            int shift,
                                            unsigned* sh_prefix, unsigned* sh_kr) {
    constexpr int BPT = (NB == 4096) ? 8 : 4;   // bins per thread
    constexpr int OWN = NB / BPT;               // owning threads
    constexpr int NW  = OWN / 32;               // owning warps
    unsigned c[BPT];
    unsigned sum = 0, s = 0;
    if (t < OWN) {
        const uint4* b4 = (const uint4*)(bins + t * BPT);
        uint4 v0 = b4[0];
        c[0] = v0.x; c[1] = v0.y; c[2] = v0.z; c[3] = v0.w;
        if (BPT == 8) {
            uint4 v1 = b4[1];
            c[4] = v1.x; c[5] = v1.y; c[6] = v1.z; c[7] = v1.w;
        }
        #pragma unroll
        for (int i = 0; i < BPT; i++) sum += c[i];
        s = sum;                                 // inclusive suffix within warp
        #pragma unroll
        for (int off = 1; off < 32; off <<= 1) {
            unsigned v = __shfl_down_sync(0xFFFFFFFFu, s, off);
            if (lane + off < 32) s += v;
        }
        if (lane == 0) wred[wid] = s;            // warp total
    }
    __syncthreads();
    if (t < 32) {                                // inclusive suffix of warp totals
        unsigned w = (lane < NW) ? wred[lane] : 0u;
        #pragma unroll
        for (int off = 1; off < NW; off <<= 1) {
            unsigned v = __shfl_down_sync(0xFFFFFFFFu, w, off);
            if (lane + off < NW) w += v;
        }
        if (lane < NW) wred[lane] = w;
    }
    __syncthreads();
    if (t < OWN) {
        // keys in bins strictly above my highest bin
        unsigned cum = (s - sum) + ((wid + 1 < NW) ? wred[wid + 1] : 0u);
        #pragma unroll
        for (int i = BPT - 1; i >= 0; i--) {
            unsigned nc = cum + c[i];
            if (cum < kr && nc >= kr) {          // crossing bin: unique globally
                *sh_prefix = prefix_base | ((unsigned)(t * BPT + i) << shift);
                *sh_kr = kr - cum;
            }
            cum = nc;
        }
    }
}

__global__ __launch_bounds__(TPB) void topk_kernel(const float* __restrict__ scores,
                                                   const float* __restrict__ Q,
                                                   const float* __restrict__ W,
                                                   const float* __restrict__ bias,
                                                   float* __restrict__ out,
                                                   float* __restrict__ outk,
                                                   int D) {
    __shared__ __align__(16) unsigned bins[4096];
    __shared__ unsigned skeys[2][KSEL];          // ping-pong for bitonic
    __shared__ unsigned wred[16];
    __shared__ float red[TPB / 32];
    __shared__ unsigned sh_prefix, sh_kr, sh_cnt;

    const int t = threadIdx.x;
    const unsigned lane = t & 31;
    const int wid = t >> 5;
    const long long row = blockIdx.x;
    const float4* src = (const float4*)(scores + row * (long long)ROWLEN);

    // ---- load 8 floats/thread, convert to sortable keys ----
    unsigned keys[8];
    {
        float4 a = src[t];
        float4 b = src[t + TPB];
        keys[0] = f2k(a.x); keys[1] = f2k(a.y); keys[2] = f2k(a.z); keys[3] = f2k(a.w);
        keys[4] = f2k(b.x); keys[5] = f2k(b.y); keys[6] = f2k(b.z); keys[7] = f2k(b.w);
    }

    // ---- fused importance gate: partial dot Q_row . W ----
    if (outk) {
        const float2* q2 = (const float2*)(Q + row * (long long)D);
        const float2* w2 = (const float2*)W;
        float s = 0.0f;
        for (int i = t; i < (D >> 1); i += TPB) {
            float2 q = q2[i], w = w2[i];
            s += q.x * w.x + q.y * w.y;
        }
        #pragma unroll
        for (int off = 16; off; off >>= 1) s += __shfl_down_sync(0xFFFFFFFFu, s, off);
        if (lane == 0) red[wid] = s;
    }

    // ---- pass A: 12-bit histogram over all keys (4096 bins) ----
    {
        const uint4 z = make_uint4(0, 0, 0, 0);
        ((uint4*)bins)[t] = z;
        ((uint4*)bins)[t + TPB] = z;
    }
    if (t == 0) sh_cnt = 0;
    __syncthreads();

    #pragma unroll
    for (int i = 0; i < 8; i++)
        atomicAdd(&bins[keys[i] >> 20], 1u);
    __syncthreads();

    if (outk && t == 0) {                        // finish gate while bins settle
        float s = bias[0];
        #pragma unroll
        for (int w = 0; w < TPB / 32; w++) s += red[w];
        float imp = 1.0f / (1.0f + expf(-s));
        outk[row] = (float)(int)(256.0f + 256.0f * imp);
    }

    scan_select<4096>(bins, wred, t, lane, wid, KSEL, 0u, 20, &sh_prefix, &sh_kr);
    __syncthreads();

    const unsigned prefA = sh_prefix;
    const unsigned krA   = sh_kr;
    __syncthreads();                             // sh reads done before next writes

    // ---- pass B: 10-bit histogram over candidates of crossing 12-bit bin ----
    if (t < 256) ((uint4*)bins)[t] = make_uint4(0, 0, 0, 0);
    __syncthreads();
    #pragma unroll
    for (int i = 0; i < 8; i++)
        if (((keys[i] ^ prefA) >> 20) == 0)
            atomicAdd(&bins[(keys[i] >> 10) & 1023u], 1u);
    __syncthreads();

    scan_select<1024>(bins, wred, t, lane, wid, krA, prefA, 10, &sh_prefix, &sh_kr);
    __syncthreads();

    const unsigned prefB = sh_prefix;
    const unsigned krB   = sh_kr;
    __syncthreads();

    // ---- pass C: final 10 bits ----
    if (t < 256) ((uint4*)bins)[t] = make_uint4(0, 0, 0, 0);
    __syncthreads();
    #pragma unroll
    for (int i = 0; i < 8; i++)
        if (((keys[i] ^ prefB) >> 10) == 0)
            atomicAdd(&bins[keys[i] & 1023u], 1u);
    __syncthreads();

    scan_select<1024>(bins, wred, t, lane, wid, krB, prefB, 0, &sh_prefix, &sh_kr);
    __syncthreads();

    const unsigned T   = sh_prefix;              // exact 512th-largest key
    const unsigned kGT = KSEL - sh_kr;           // # keys strictly greater than T

    // ---- compact keys > T via ballot-aggregated atomics ----
    const unsigned lt_mask = (lane == 0) ? 0u : (0xFFFFFFFFu >> (32 - lane));
    #pragma unroll
    for (int i = 0; i < 8; i++) {
        bool p = keys[i] > T;
        unsigned bal = __ballot_sync(0xFFFFFFFFu, p);
        unsigned base = 0;
        if (lane == 0 && bal) base = atomicAdd(&sh_cnt, (unsigned)__popc(bal));
        base = __shfl_sync(0xFFFFFFFFu, base, 0);
        if (p) skeys[0][base + __popc(bal & lt_mask)] = keys[i];
    }
    __syncthreads();
    if ((unsigned)t >= kGT) skeys[0][t] = T;     // pad ties
    __syncthreads();

    // ---- hybrid bitonic sort (descending), element t in register v ----
    unsigned v = skeys[0][t];
    int buf = 0;

    #pragma unroll
    for (int k2 = 2; k2 <= 32; k2 <<= 1) {       // shfl-only stages
        #pragma unroll
        for (int j = k2 >> 1; j > 0; j >>= 1) {
            unsigned o = __shfl_xor_sync(0xFFFFFFFFu, v, j);
            bool up    = ((t & k2) == 0);
            bool lower = ((t & j)  == 0);
            v = (up == lower) ? max(v, o) : min(v, o);
        }
    }
    #pragma unroll 1
    for (int k2 = 64; k2 <= KSEL; k2 <<= 1) {    // smem (1 bar/stage) + shfl tail
        #pragma unroll 1
        for (int j = k2 >> 1; j >= 32; j >>= 1) {
            buf ^= 1;
            skeys[buf][t] = v;
            __syncthreads();
            unsigned o = skeys[buf][t ^ j];
            bool up    = ((t & k2) == 0);
            bool lower = ((t & j)  == 0);
            v = (up == lower) ? max(v, o) : min(v, o);
        }
        #pragma unroll
        for (int j = 16; j > 0; j >>= 1) {
            unsigned o = __shfl_xor_sync(0xFFFFFFFFu, v, j);
            bool up    = ((t & k2) == 0);
            bool lower = ((t & j)  == 0);
            v = (up == lower) ? max(v, o) : min(v, o);
        }
    }

    out[row * (long long)KSEL + t] = k2f(v);
}

extern "C" void kernel_launch(void* const* d_in, const int* in_sizes, int n_in,
                              void* d_out, int out_size) {
    const float* Q      = (const float*)d_in[0];
    const float* scores = (const float*)d_in[1];
    const float* W      = (const float*)d_in[2];
    const float* b      = (const float*)d_in[3];

    const int D = in_sizes[2];                        // 1024
    const long long BS = (long long)in_sizes[0] / D;  // B*S = 16384

    float* out  = (float*)d_out;
    float* outk = ((long long)out_size >= BS * KSEL + BS) ? out + BS * KSEL : nullptr;

    topk_kernel<<<(unsigned)BS, TPB>>>(scores, Q, W, b, out, outk, D);
}

// round 5
// speedup vs baseline: 1.8026x; 1.2434x over previous
#include <cuda_runtime.h>
#include <cuda_bf16.h>

// AdaptiveTokenSelector:
//   out[0 .. B*S*512)   = top-512 values per score row, sorted descending (f32)
//   out[B*S*512 .. +BS) = k_per_query = int(256 + 256*sigmoid(Q.W + b)) as f32
//
// One CTA (512 threads) per row, 8 register keys/thread:
//   - 12/10/10-bit MSD radix select (4096-bin pass A, 1024-bin passes B/C)
//   - block suffix-scan to find the crossing bin
//   - ballot-aggregated compaction of keys > threshold, pad with threshold
//   - V=4 register bitonic sort on 128 threads (4 warps); other 12 warps exit:
//     j<4 in-register, 4<=j<=64 via shfl, j in {128,256} via smem + bar.sync 1
//   - fused importance gate

#define TPB      512
#define ROWLEN   4096
#define KSEL     512
#define SORT_T   128

__device__ __forceinline__ unsigned f2k(float f) {
    unsigned u = __float_as_uint(f);
    return u ^ ((unsigned)((int)u >> 31) | 0x80000000u);
}

__device__ __forceinline__ float k2f(unsigned k) {
    unsigned u = (k & 0x80000000u) ? (k ^ 0x80000000u) : ~k;
    return __uint_as_float(u);
}

// compare-exchange: if up, a gets max; else a gets min
__device__ __forceinline__ void cswap(unsigned& a, unsigned& b, bool up) {
    unsigned hi = max(a, b), lo = min(a, b);
    a = up ? hi : lo;
    b = up ? lo : hi;
}

// Block-wide suffix scan over NB bins; finds the bin holding the kr-th largest
// key (bins ascending by key). Writes new prefix/kr. 2 internal barriers.
template<int NB>
__device__ __forceinline__ void scan_select(const unsigned* __restrict__ bins,
                                            unsigned* wred,
                                            int t, unsigned lane, int wid,
                                            unsigned kr, unsigned prefix_base,
                                            int shift,
                                            unsigned* sh_prefix, unsigned* sh_kr) {
    constexpr int BPT = (NB == 4096) ? 8 : 4;
    constexpr int OWN = NB / BPT;
    constexpr int NW  = OWN / 32;
    unsigned c[BPT];
    unsigned sum = 0, s = 0;
    if (t < OWN) {
        const uint4* b4 = (const uint4*)(bins + t * BPT);
        uint4 v0 = b4[0];
        c[0] = v0.x; c[1] = v0.y; c[2] = v0.z; c[3] = v0.w;
        if (BPT == 8) {
            uint4 v1 = b4[1];
            c[4] = v1.x; c[5] = v1.y; c[6] = v1.z; c[7] = v1.w;
        }
        #pragma unroll
        for (int i = 0; i < BPT; i++) sum += c[i];
        s = sum;
        #pragma unroll
        for (int off = 1; off < 32; off <<= 1) {
            unsigned v = __shfl_down_sync(0xFFFFFFFFu, s, off);
            if (lane + off < 32) s += v;
        }
        if (lane == 0) wred[wid] = s;
    }
    __syncthreads();
    if (t < 32) {
        unsigned w = (lane < NW) ? wred[lane] : 0u;
        #pragma unroll
        for (int off = 1; off < NW; off <<= 1) {
            unsigned v = __shfl_down_sync(0xFFFFFFFFu, w, off);
            if (lane + off < NW) w += v;
        }
        if (lane < NW) wred[lane] = w;
    }
    __syncthreads();
    if (t < OWN) {
        unsigned cum = (s - sum) + ((wid + 1 < NW) ? wred[wid + 1] : 0u);
        #pragma unroll
        for (int i = BPT - 1; i >= 0; i--) {
            unsigned nc = cum + c[i];
            if (cum < kr && nc >= kr) {
                *sh_prefix = prefix_base | ((unsigned)(t * BPT + i) << shift);
                *sh_kr = kr - cum;
            }
            cum = nc;
        }
    }
}

__global__ __launch_bounds__(TPB) void topk_kernel(const float* __restrict__ scores,
                                                   const float* __restrict__ Q,
                                                   const float* __restrict__ W,
                                                   const float* __restrict__ bias,
                                                   float* __restrict__ out,
                                                   float* __restrict__ outk,
                                                   int D) {
    __shared__ __align__(16) unsigned bins[4096];
    __shared__ __align__(16) unsigned skeys[2][KSEL];
    __shared__ unsigned wred[16];
    __shared__ float red[TPB / 32];
    __shared__ unsigned sh_prefix, sh_kr, sh_cnt;

    const int t = threadIdx.x;
    const unsigned lane = t & 31;
    const int wid = t >> 5;
    const long long row = blockIdx.x;
    const float4* src = (const float4*)(scores + row * (long long)ROWLEN);

    // ---- load 8 floats/thread, convert to sortable keys ----
    unsigned keys[8];
    {
        float4 a = src[t];
        float4 b = src[t + TPB];
        keys[0] = f2k(a.x); keys[1] = f2k(a.y); keys[2] = f2k(a.z); keys[3] = f2k(a.w);
        keys[4] = f2k(b.x); keys[5] = f2k(b.y); keys[6] = f2k(b.z); keys[7] = f2k(b.w);
    }

    // ---- fused importance gate: partial dot Q_row . W ----
    if (outk) {
        const float2* q2 = (const float2*)(Q + row * (long long)D);
        const float2* w2 = (const float2*)W;
        float s = 0.0f;
        for (int i = t; i < (D >> 1); i += TPB) {
            float2 q = q2[i], w = w2[i];
            s += q.x * w.x + q.y * w.y;
        }
        #pragma unroll
        for (int off = 16; off; off >>= 1) s += __shfl_down_sync(0xFFFFFFFFu, s, off);
        if (lane == 0) red[wid] = s;
    }

    // ---- pass A: 12-bit histogram (4096 bins) ----
    {
        const uint4 z = make_uint4(0, 0, 0, 0);
        ((uint4*)bins)[t] = z;
        ((uint4*)bins)[t + TPB] = z;
    }
    if (t == 0) sh_cnt = 0;
    __syncthreads();

    #pragma unroll
    for (int i = 0; i < 8; i++)
        atomicAdd(&bins[keys[i] >> 20], 1u);
    __syncthreads();

    if (outk && t == 0) {
        float s = bias[0];
        #pragma unroll
        for (int w = 0; w < TPB / 32; w++) s += red[w];
        float imp = 1.0f / (1.0f + expf(-s));
        outk[row] = (float)(int)(256.0f + 256.0f * imp);
    }

    scan_select<4096>(bins, wred, t, lane, wid, KSEL, 0u, 20, &sh_prefix, &sh_kr);
    __syncthreads();                     // sh_prefix visible; all bin reads done

    const unsigned prefA = sh_prefix;
    const unsigned krA   = sh_kr;
    if (t < 256) ((uint4*)bins)[t] = make_uint4(0, 0, 0, 0);
    __syncthreads();

    // ---- pass B: 10-bit histogram over crossing-bin candidates ----
    #pragma unroll
    for (int i = 0; i < 8; i++)
        if (((keys[i] ^ prefA) >> 20) == 0)
            atomicAdd(&bins[(keys[i] >> 10) & 1023u], 1u);
    __syncthreads();

    scan_select<1024>(bins, wred, t, lane, wid, krA, prefA, 10, &sh_prefix, &sh_kr);
    __syncthreads();

    const unsigned prefB = sh_prefix;
    const unsigned krB   = sh_kr;
    if (t < 256) ((uint4*)bins)[t] = make_uint4(0, 0, 0, 0);
    __syncthreads();

    // ---- pass C: final 10 bits ----
    #pragma unroll
    for (int i = 0; i < 8; i++)
        if (((keys[i] ^ prefB) >> 10) == 0)
            atomicAdd(&bins[keys[i] & 1023u], 1u);
    __syncthreads();

    scan_select<1024>(bins, wred, t, lane, wid, krB, prefB, 0, &sh_prefix, &sh_kr);
    __syncthreads();

    const unsigned T   = sh_prefix;              // exact 512th-largest key
    const unsigned kGT = KSEL - sh_kr;           // # keys strictly greater than T

    // ---- compact keys > T via ballot-aggregated atomics ----
    const unsigned lt_mask = (lane == 0) ? 0u : (0xFFFFFFFFu >> (32 - lane));
    #pragma unroll
    for (int i = 0; i < 8; i++) {
        bool p = keys[i] > T;
        unsigned bal = __ballot_sync(0xFFFFFFFFu, p);
        unsigned base = 0;
        if (lane == 0 && bal) base = atomicAdd(&sh_cnt, (unsigned)__popc(bal));
        base = __shfl_sync(0xFFFFFFFFu, base, 0);
        if (p) skeys[0][base + __popc(bal & lt_mask)] = keys[i];
    }
    if ((unsigned)t >= kGT) skeys[0][t] = T;     // pad ties (disjoint indices)
    __syncthreads();

    // ---- V=4 register bitonic sort on 4 warps; everyone else leaves ----
    if (t >= SORT_T) return;

    uint4 vv = ((const uint4*)skeys[0])[t];      // elements 4t..4t+3
    unsigned v0 = vv.x, v1 = vv.y, v2 = vv.z, v3 = vv.w;
    int buf = 0;

    // in-register double stage for k2>=4: j=2 then j=1 (dir uniform per thread)
    #define INREG(K2) { \
        bool up = (t & ((K2) >> 2)) == 0; \
        cswap(v0, v2, up); cswap(v1, v3, up); \
        cswap(v0, v1, up); cswap(v2, v3, up); }

    // shfl stage, 4 <= J <= 64 (lane distance J/4 <= 16)
    #define XSTAGE(K2, J) { \
        bool dir = ((t & ((K2) >> 2)) == 0) == ((t & ((J) >> 2)) == 0); \
        unsigned o0 = __shfl_xor_sync(0xFFFFFFFFu, v0, (J) >> 2); \
        unsigned o1 = __shfl_xor_sync(0xFFFFFFFFu, v1, (J) >> 2); \
        unsigned o2 = __shfl_xor_sync(0xFFFFFFFFu, v2, (J) >> 2); \
        unsigned o3 = __shfl_xor_sync(0xFFFFFFFFu, v3, (J) >> 2); \
        v0 = dir ? max(v0, o0) : min(v0, o0); \
        v1 = dir ? max(v1, o1) : min(v1, o1); \
        v2 = dir ? max(v2, o2) : min(v2, o2); \
        v3 = dir ? max(v3, o3) : min(v3, o3); }

    // cross-warp stage via double-buffered smem, J in {128, 256}
    #define MSTAGE(K2, J) { \
        buf ^= 1; \
        ((uint4*)skeys[buf])[t] = make_uint4(v0, v1, v2, v3); \
        asm volatile("bar.sync 1, %0;" :: "r"(SORT_T) : "memory"); \
        uint4 o = ((const uint4*)skeys[buf])[t ^ ((J) >> 2)]; \
        bool dir = ((t & ((K2) >> 2)) == 0) == ((t & ((J) >> 2)) == 0); \
        v0 = dir ? max(v0, o.x) : min(v0, o.x); \
        v1 = dir ? max(v1, o.y) : min(v1, o.y); \
        v2 = dir ? max(v2, o.z) : min(v2, o.z); \
        v3 = dir ? max(v3, o.w) : min(v3, o.w); }

    // k2 = 2 (compile-time directions)
    cswap(v0, v1, true); cswap(v2, v3, false);
    // k2 = 4
    INREG(4)
    // k2 = 8
    XSTAGE(8, 4)   INREG(8)
    // k2 = 16
    XSTAGE(16, 8)  XSTAGE(16, 4)  INREG(16)
    // k2 = 32
    XSTAGE(32, 16) XSTAGE(32, 8)  XSTAGE(32, 4)  INREG(32)
    // k2 = 64
    XSTAGE(64, 32) XSTAGE(64, 16) XSTAGE(64, 8)  XSTAGE(64, 4)  INREG(64)
    // k2 = 128
    XSTAGE(128, 64) XSTAGE(128, 32) XSTAGE(128, 16) XSTAGE(128, 8) XSTAGE(128, 4)
    INREG(128)
    // k2 = 256
    MSTAGE(256, 128)
    XSTAGE(256, 64) XSTAGE(256, 32) XSTAGE(256, 16) XSTAGE(256, 8) XSTAGE(256, 4)
    INREG(256)
    // k2 = 512
    MSTAGE(512, 256) MSTAGE(512, 128)
    XSTAGE(512, 64) XSTAGE(512, 32) XSTAGE(512, 16) XSTAGE(512, 8) XSTAGE(512, 4)
    INREG(512)

    float4 r;
    r.x = k2f(v0); r.y = k2f(v1); r.z = k2f(v2); r.w = k2f(v3);
    ((float4*)(out + row * (long long)KSEL))[t] = r;
}

extern "C" void kernel_launch(void* const* d_in, const int* in_sizes, int n_in,
                              void* d_out, int out_size) {
    const float* Q      = (const float*)d_in[0];
    const float* scores = (const float*)d_in[1];
    const float* W      = (const float*)d_in[2];
    const float* b      = (const float*)d_in[3];

    const int D = in_sizes[2];                        // 1024
    const long long BS = (long long)in_sizes[0] / D;  // B*S = 16384

    float* out  = (float*)d_out;
    float* outk = ((long long)out_size >= BS * KSEL + BS) ? out + BS * KSEL : nullptr;

    topk_kernel<<<(unsigned)BS, TPB>>>(scores, Q, W, b, out, outk, D);
}

// round 6
// speedup vs baseline: 1.8331x; 1.0169x over previous
#include <cuda_runtime.h>
#include <cuda_bf16.h>

// AdaptiveTokenSelector:
//   out[0 .. B*S*512)   = top-512 values per score row, sorted descending (f32)
//   out[B*S*512 .. +BS) = k_per_query = int(256 + 256*sigmoid(Q.W + b)) as f32
//
// One CTA (512 threads) per row, 8 register keys/thread:
//   - pass A: 12-bit histogram over keys >= MKEY only (bin-boundary-aligned
//     prefilter; exact fallback to full histogram if filtered total < 512)
//   - passes B/C: 10-bit histograms over ~200 candidates
//   - block suffix-scan finds the crossing bin (also yields total count)
//   - compaction: warp exclusive scan + 1 shared atomic per warp
//   - V=4 register bitonic sort on 128 threads (4 warps); other warps exit
//   - fused importance gate

#define TPB      512
#define ROWLEN   4096
#define KSEL     512
#define SORT_T   128
#define MKEY     0xBF000000u   /* f2k(0.5f): aligned to 12-bit bin 3056 */

__device__ __forceinline__ unsigned f2k(float f) {
    unsigned u = __float_as_uint(f);
    return u ^ ((unsigned)((int)u >> 31) | 0x80000000u);
}

__device__ __forceinline__ float k2f(unsigned k) {
    unsigned u = (k & 0x80000000u) ? (k ^ 0x80000000u) : ~k;
    return __uint_as_float(u);
}

__device__ __forceinline__ void cswap(unsigned& a, unsigned& b, bool up) {
    unsigned hi = max(a, b), lo = min(a, b);
    a = up ? hi : lo;
    b = up ? lo : hi;
}

// Block-wide suffix scan over NB bins; finds the bin holding the kr-th largest
// key (bins ascending by key). Writes new prefix/kr. After the caller's next
// __syncthreads(), wred[0] holds the TOTAL count across all bins.
template<int NB>
__device__ __forceinline__ void scan_select(const unsigned* __restrict__ bins,
                                            unsigned* wred,
                                            int t, unsigned lane, int wid,
                                            unsigned kr, unsigned prefix_base,
                                            int shift,
                                            unsigned* sh_prefix, unsigned* sh_kr) {
    constexpr int BPT = (NB == 4096) ? 8 : 4;
    constexpr int OWN = NB / BPT;
    constexpr int NW  = OWN / 32;
    unsigned c[BPT];
    unsigned sum = 0, s = 0;
    if (t < OWN) {
        const uint4* b4 = (const uint4*)(bins + t * BPT);
        uint4 v0 = b4[0];
        c[0] = v0.x; c[1] = v0.y; c[2] = v0.z; c[3] = v0.w;
        if (BPT == 8) {
            uint4 v1 = b4[1];
            c[4] = v1.x; c[5] = v1.y; c[6] = v1.z; c[7] = v1.w;
        }
        #pragma unroll
        for (int i = 0; i < BPT; i++) sum += c[i];
        s = sum;
        #pragma unroll
        for (int off = 1; off < 32; off <<= 1) {
            unsigned v = __shfl_down_sync(0xFFFFFFFFu, s, off);
            if (lane + off < 32) s += v;
        }
        if (lane == 0) wred[wid] = s;
    }
    __syncthreads();
    if (t < 32) {
        unsigned w = (lane < NW) ? wred[lane] : 0u;
        #pragma unroll
        for (int off = 1; off < NW; off <<= 1) {
            unsigned v = __shfl_down_sync(0xFFFFFFFFu, w, off);
            if (lane + off < NW) w += v;
        }
        if (lane < NW) wred[lane] = w;   // wred[0] = total
    }
    __syncthreads();
    if (t < OWN) {
        unsigned cum = (s - sum) + ((wid + 1 < NW) ? wred[wid + 1] : 0u);
        #pragma unroll
        for (int i = BPT - 1; i >= 0; i--) {
            unsigned nc = cum + c[i];
            if (cum < kr && nc >= kr) {
                *sh_prefix = prefix_base | ((unsigned)(t * BPT + i) << shift);
                *sh_kr = kr - cum;
            }
            cum = nc;
        }
    }
}

__global__ __launch_bounds__(TPB) void topk_kernel(const float* __restrict__ scores,
                                                   const float* __restrict__ Q,
                                                   const float* __restrict__ W,
                                                   const float* __restrict__ bias,
                                                   float* __restrict__ out,
                                                   float* __restrict__ outk,
                                                   int D) {
    __shared__ __align__(16) unsigned bins[4096];
    __shared__ __align__(16) unsigned skeys[2][KSEL];
    __shared__ unsigned wred[16];
    __shared__ float red[TPB / 32];
    __shared__ unsigned sh_prefix, sh_kr, sh_cnt;

    const int t = threadIdx.x;
    const unsigned lane = t & 31;
    const int wid = t >> 5;
    const long long row = blockIdx.x;
    const float4* src = (const float4*)(scores + row * (long long)ROWLEN);

    // ---- load 8 floats/thread, convert to sortable keys ----
    unsigned keys[8];
    {
        float4 a = src[t];
        float4 b = src[t + TPB];
        keys[0] = f2k(a.x); keys[1] = f2k(a.y); keys[2] = f2k(a.z); keys[3] = f2k(a.w);
        keys[4] = f2k(b.x); keys[5] = f2k(b.y); keys[6] = f2k(b.z); keys[7] = f2k(b.w);
    }

    // ---- fused importance gate: partial dot Q_row . W ----
    if (outk) {
        const float2* q2 = (const float2*)(Q + row * (long long)D);
        const float2* w2 = (const float2*)W;
        float s = 0.0f;
        for (int i = t; i < (D >> 1); i += TPB) {
            float2 q = q2[i], w = w2[i];
            s += q.x * w.x + q.y * w.y;
        }
        #pragma unroll
        for (int off = 16; off; off >>= 1) s += __shfl_down_sync(0xFFFFFFFFu, s, off);
        if (lane == 0) red[wid] = s;
    }

    // ---- pass A: filtered 12-bit histogram (keys >= MKEY only) ----
    {
        const uint4 z = make_uint4(0, 0, 0, 0);
        ((uint4*)bins)[t] = z;
        ((uint4*)bins)[t + TPB] = z;
    }
    if (t == 0) sh_cnt = 0;
    __syncthreads();

    #pragma unroll
    for (int i = 0; i < 8; i++)
        if (keys[i] >= MKEY)
            atomicAdd(&bins[keys[i] >> 20], 1u);
    __syncthreads();

    if (outk && t == 0) {
        float s = bias[0];
        #pragma unroll
        for (int w = 0; w < TPB / 32; w++) s += red[w];
        float imp = 1.0f / (1.0f + expf(-s));
        outk[row] = (float)(int)(256.0f + 256.0f * imp);
    }

    scan_select<4096>(bins, wred, t, lane, wid, KSEL, 0u, 20, &sh_prefix, &sh_kr);
    __syncthreads();

    // exactness fallback: if fewer than KSEL keys passed the prefilter,
    // redo pass A over ALL keys (never taken for N(0,1)-like rows)
    if (wred[0] < KSEL) {
        {
            const uint4 z = make_uint4(0, 0, 0, 0);
            ((uint4*)bins)[t] = z;
            ((uint4*)bins)[t + TPB] = z;
        }
        __syncthreads();
        #pragma unroll
        for (int i = 0; i < 8; i++)
            atomicAdd(&bins[keys[i] >> 20], 1u);
        __syncthreads();
        scan_select<4096>(bins, wred, t, lane, wid, KSEL, 0u, 20, &sh_prefix, &sh_kr);
        __syncthreads();
    }

    const unsigned prefA = sh_prefix;
    const unsigned krA   = sh_kr;
    if (t < 256) ((uint4*)bins)[t] = make_uint4(0, 0, 0, 0);
    __syncthreads();

    // ---- pass B: 10-bit histogram over crossing-bin candidates ----
    #pragma unroll
    for (int i = 0; i < 8; i++)
        if (((keys[i] ^ prefA) >> 20) == 0)
            atomicAdd(&bins[(keys[i] >> 10) & 1023u], 1u);
    __syncthreads();

    scan_select<1024>(bins, wred, t, lane, wid, krA, prefA, 10, &sh_prefix, &sh_kr);
    __syncthreads();

    const unsigned prefB = sh_prefix;
    const unsigned krB   = sh_kr;
    if (t < 256) ((uint4*)bins)[t] = make_uint4(0, 0, 0, 0);
    __syncthreads();

    // ---- pass C: final 10 bits ----
    #pragma unroll
    for (int i = 0; i < 8; i++)
        if (((keys[i] ^ prefB) >> 10) == 0)
            atomicAdd(&bins[keys[i] & 1023u], 1u);
    __syncthreads();

    scan_select<1024>(bins, wred, t, lane, wid, krB, prefB, 0, &sh_prefix, &sh_kr);
    __syncthreads();

    const unsigned T   = sh_prefix;              // exact 512th-largest key
    const unsigned kGT = KSEL - sh_kr;           // # keys strictly greater than T

    // ---- compact keys > T: warp exclusive scan + 1 atomic per warp ----
    {
        unsigned flags = 0, pcnt = 0;
        #pragma unroll
        for (int i = 0; i < 8; i++) {
            bool p = keys[i] > T;
            flags |= (unsigned)p << i;
            pcnt += p;
        }
        unsigned incl = pcnt;                    // inclusive warp scan
        #pragma unroll
        for (int d = 1; d < 32; d <<= 1) {
            unsigned v = __shfl_up_sync(0xFFFFFFFFu, incl, d);
            if (lane >= d) incl += v;
        }
        unsigned base = 0;
        if (lane == 31 && incl) base = atomicAdd(&sh_cnt, incl);
        base = __shfl_sync(0xFFFFFFFFu, base, 31);
        unsigned pos = base + incl - pcnt;
        #pragma unroll
        for (int i = 0; i < 8; i++)
            if ((flags >> i) & 1) skeys[0][pos++] = keys[i];
    }
    if ((unsigned)t >= kGT) skeys[0][t] = T;     // pad ties (disjoint indices)
    __syncthreads();

    // ---- V=4 register bitonic sort on 4 warps; everyone else leaves ----
    if (t >= SORT_T) return;

    uint4 vv = ((const uint4*)skeys[0])[t];      // elements 4t..4t+3
    unsigned v0 = vv.x, v1 = vv.y, v2 = vv.z, v3 = vv.w;
    int buf = 0;

    #define INREG(K2) { \
        bool up = (t & ((K2) >> 2)) == 0; \
        cswap(v0, v2, up); cswap(v1, v3, up); \
        cswap(v0, v1, up); cswap(v2, v3, up); }

    #define XSTAGE(K2, J) { \
        bool dir = ((t & ((K2) >> 2)) == 0) == ((t & ((J) >> 2)) == 0); \
        unsigned o0 = __shfl_xor_sync(0xFFFFFFFFu, v0, (J) >> 2); \
        unsigned o1 = __shfl_xor_sync(0xFFFFFFFFu, v1, (J) >> 2); \
        unsigned o2 = __shfl_xor_sync(0xFFFFFFFFu, v2, (J) >> 2); \
        unsigned o3 = __shfl_xor_sync(0xFFFFFFFFu, v3, (J) >> 2); \
        v0 = dir ? max(v0, o0) : min(v0, o0); \
        v1 = dir ? max(v1, o1) : min(v1, o1); \
        v2 = dir ? max(v2, o2) : min(v2, o2); \
        v3 = dir ? max(v3, o3) : min(v3, o3); }

    #define MSTAGE(K2, J) { \
        buf ^= 1; \
        ((uint4*)skeys[buf])[t] = make_uint4(v0, v1, v2, v3); \
        asm volatile("bar.sync 1, %0;" :: "r"(SORT_T) : "memory"); \
        uint4 o = ((const uint4*)skeys[buf])[t ^ ((J) >> 2)]; \
        bool dir = ((t & ((K2) >> 2)) == 0) == ((t & ((J) >> 2)) == 0); \
        v0 = dir ? max(v0, o.x) : min(v0, o.x); \
        v1 = dir ? max(v1, o.y) : min(v1, o.y); \
        v2 = dir ? max(v2, o.z) : min(v2, o.z); \
        v3 = dir ? max(v3, o.w) : min(v3, o.w); }

    cswap(v0, v1, true); cswap(v2, v3, false);       // k2 = 2
    INREG(4)                                          // k2 = 4
    XSTAGE(8, 4)   INREG(8)                           // k2 = 8
    XSTAGE(16, 8)  XSTAGE(16, 4)  INREG(16)           // k2 = 16
    XSTAGE(32, 16) XSTAGE(32, 8)  XSTAGE(32, 4)  INREG(32)
    XSTAGE(64, 32) XSTAGE(64, 16) XSTAGE(64, 8)  XSTAGE(64, 4)  INREG(64)
    XSTAGE(128, 64) XSTAGE(128, 32) XSTAGE(128, 16) XSTAGE(128, 8) XSTAGE(128, 4)
    INREG(128)
    MSTAGE(256, 128)
    XSTAGE(256, 64) XSTAGE(256, 32) XSTAGE(256, 16) XSTAGE(256, 8) XSTAGE(256, 4)
    INREG(256)
    MSTAGE(512, 256) MSTAGE(512, 128)
    XSTAGE(512, 64) XSTAGE(512, 32) XSTAGE(512, 16) XSTAGE(512, 8) XSTAGE(512, 4)
    INREG(512)

    float4 r;
    r.x = k2f(v0); r.y = k2f(v1); r.z = k2f(v2); r.w = k2f(v3);
    ((float4*)(out + row * (long long)KSEL))[t] = r;
}

extern "C" void kernel_launch(void* const* d_in, const int* in_sizes, int n_in,
                              void* d_out, int out_size) {
    const float* Q      = (const float*)d_in[0];
    const float* scores = (const float*)d_in[1];
    const float* W      = (const float*)d_in[2];
    const float* b      = (const float*)d_in[3];

    const int D = in_sizes[2];                        // 1024
    const long long BS = (long long)in_sizes[0] / D;  // B*S = 16384

    float* out  = (float*)d_out;
    float* outk = ((long long)out_size >= BS * KSEL + BS) ? out + BS * KSEL : nullptr;

    topk_kernel<<<(unsigned)BS, TPB>>>(scores, Q, W, b, out, outk, D);
}

// round 7
// speedup vs baseline: 1.8508x; 1.0096x over previous
#include <cuda_runtime.h>
#include <cuda_bf16.h>

// AdaptiveTokenSelector:
//   out[0 .. B*S*512)   = top-512 values per score row, sorted descending (f32)
//   out[B*S*512 .. +BS) = k_per_query = int(256 + 256*sigmoid(Q.W + b)) as f32
//
// One CTA (512 threads) per row, 8 register keys/thread:
//   - pass A: 12-bit histogram over keys >= filter (filter starts at MKEY, a
//     bin-boundary-aligned prefilter; exact fallback loop retries with 0)
//   - passes B/C: 10-bit histograms over ~200 candidates
//   - block suffix-scan finds the crossing bin (wred[0] = total count)
//   - compaction: warp exclusive scan + 1 shared atomic per warp
//   - V=4 register bitonic sort on 128 threads (4 warps); other warps exit
//   - fused importance gate
//   - __launch_bounds__(512,4) pins regs <= 32 for 4 CTAs/SM

#define TPB      512
#define ROWLEN   4096
#define KSEL     512
#define SORT_T   128
#define MKEY     0xBF000000u   /* f2k(0.5f): aligned to 12-bit bin 3056 */

__device__ __forceinline__ unsigned f2k(float f) {
    unsigned u = __float_as_uint(f);
    return u ^ ((unsigned)((int)u >> 31) | 0x80000000u);
}

__device__ __forceinline__ float k2f(unsigned k) {
    unsigned u = (k & 0x80000000u) ? (k ^ 0x80000000u) : ~k;
    return __uint_as_float(u);
}

__device__ __forceinline__ void cswap(unsigned& a, unsigned& b, bool up) {
    unsigned hi = max(a, b), lo = min(a, b);
    a = up ? hi : lo;
    b = up ? lo : hi;
}

// Block-wide suffix scan over NB bins; finds the bin holding the kr-th largest
// key (bins ascending by key). Writes new prefix/kr. After the caller's next
// __syncthreads(), wred[0] holds the TOTAL count across all bins.
template<int NB>
__device__ __forceinline__ void scan_select(const unsigned* __restrict__ bins,
                                            unsigned* wred,
                                            int t, unsigned lane, int wid,
                                            unsigned kr, unsigned prefix_base,
                                            int shift,
                                            unsigned* sh_prefix, unsigned* sh_kr) {
    constexpr int BPT = (NB == 4096) ? 8 : 4;
    constexpr int OWN = NB / BPT;
    constexpr int NW  = OWN / 32;
    unsigned c[BPT];
    unsigned sum = 0, s = 0;
    if (t < OWN) {
        const uint4* b4 = (const uint4*)(bins + t * BPT);
        uint4 v0 = b4[0];
        c[0] = v0.x; c[1] = v0.y; c[2] = v0.z; c[3] = v0.w;
        if (BPT == 8) {
            uint4 v1 = b4[1];
            c[4] = v1.x; c[5] = v1.y; c[6] = v1.z; c[7] = v1.w;
        }
        #pragma unroll
        for (int i = 0; i < BPT; i++) sum += c[i];
        s = sum;
        #pragma unroll
        for (int off = 1; off < 32; off <<= 1) {
            unsigned v = __shfl_down_sync(0xFFFFFFFFu, s, off);
            if (lane + off < 32) s += v;
        }
        if (lane == 0) wred[wid] = s;
    }
    __syncthreads();
    if (t < 32) {
        unsigned w = (lane < NW) ? wred[lane] : 0u;
        #pragma unroll
        for (int off = 1; off < NW; off <<= 1) {
            unsigned v = __shfl_down_sync(0xFFFFFFFFu, w, off);
            if (lane + off < NW) w += v;
        }
        if (lane < NW) wred[lane] = w;   // wred[0] = total
    }
    __syncthreads();
    if (t < OWN) {
        unsigned cum = (s - sum) + ((wid + 1 < NW) ? wred[wid + 1] : 0u);
        #pragma unroll
        for (int i = BPT - 1; i >= 0; i--) {
            unsigned nc = cum + c[i];
            if (cum < kr && nc >= kr) {
                *sh_prefix = prefix_base | ((unsigned)(t * BPT + i) << shift);
                *sh_kr = kr - cum;
            }
            cum = nc;
        }
    }
}

__global__ __launch_bounds__(TPB, 4) void topk_kernel(const float* __restrict__ scores,
                                                      const float* __restrict__ Q,
                                                      const float* __restrict__ W,
                                                      const float* __restrict__ bias,
                                                      float* __restrict__ out,
                                                      float* __restrict__ outk,
                                                      int D) {
    __shared__ __align__(16) unsigned bins[4096];
    __shared__ __align__(16) unsigned skeys[2][KSEL];
    __shared__ unsigned wred[16];
    __shared__ float red[TPB / 32];
    __shared__ unsigned sh_prefix, sh_kr, sh_cnt;

    const int t = threadIdx.x;
    const unsigned lane = t & 31;
    const int wid = t >> 5;
    const long long row = blockIdx.x;
    const float4* src = (const float4*)(scores + row * (long long)ROWLEN);

    // ---- load 8 floats/thread, convert to sortable keys ----
    unsigned keys[8];
    {
        float4 a = src[t];
        float4 b = src[t + TPB];
        keys[0] = f2k(a.x); keys[1] = f2k(a.y); keys[2] = f2k(a.z); keys[3] = f2k(a.w);
        keys[4] = f2k(b.x); keys[5] = f2k(b.y); keys[6] = f2k(b.z); keys[7] = f2k(b.w);
    }

    // ---- fused importance gate: partial dot Q_row . W ----
    if (outk) {
        const float2* q2 = (const float2*)(Q + row * (long long)D);
        const float2* w2 = (const float2*)W;
        float s = 0.0f;
        for (int i = t; i < (D >> 1); i += TPB) {
            float2 q = q2[i], w = w2[i];
            s += q.x * w.x + q.y * w.y;
        }
        #pragma unroll
        for (int off = 16; off; off >>= 1) s += __shfl_down_sync(0xFFFFFFFFu, s, off);
        if (lane == 0) red[wid] = s;
    }

    if (t == 0) sh_cnt = 0;

    // ---- pass A: filtered 12-bit histogram; exact fallback loop ----
    unsigned filt = MKEY;
    for (;;) {
        {
            const uint4 z = make_uint4(0, 0, 0, 0);
            ((uint4*)bins)[t] = z;
            ((uint4*)bins)[t + TPB] = z;
        }
        __syncthreads();

        #pragma unroll
        for (int i = 0; i < 8; i++)
            if (keys[i] >= filt)
                atomicAdd(&bins[keys[i] >> 20], 1u);
        __syncthreads();

        if (filt == MKEY && outk && t == 0) {    // finish gate once
            float s = bias[0];
            #pragma unroll
            for (int w = 0; w < TPB / 32; w++) s += red[w];
            float imp = 1.0f / (1.0f + expf(-s));
            outk[row] = (float)(int)(256.0f + 256.0f * imp);
        }

        scan_select<4096>(bins, wred, t, lane, wid, KSEL, 0u, 20, &sh_prefix, &sh_kr);
        __syncthreads();

        if (wred[0] >= KSEL || filt == 0u) break;
        filt = 0u;                               // retry unfiltered (exactness)
    }

    const unsigned prefA = sh_prefix;
    const unsigned krA   = sh_kr;
    if (t < 256) ((uint4*)bins)[t] = make_uint4(0, 0, 0, 0);
    __syncthreads();

    // ---- pass B: 10-bit histogram over crossing-bin candidates ----
    #pragma unroll
    for (int i = 0; i < 8; i++)
        if (((keys[i] ^ prefA) >> 20) == 0)
            atomicAdd(&bins[(keys[i] >> 10) & 1023u], 1u);
    __syncthreads();

    scan_select<1024>(bins, wred, t, lane, wid, krA, prefA, 10, &sh_prefix, &sh_kr);
    __syncthreads();

    const unsigned prefB = sh_prefix;
    const unsigned krB   = sh_kr;
    if (t < 256) ((uint4*)bins)[t] = make_uint4(0, 0, 0, 0);
    __syncthreads();

    // ---- pass C: final 10 bits ----
    #pragma unroll
    for (int i = 0; i < 8; i++)
        if (((keys[i] ^ prefB) >> 10) == 0)
            atomicAdd(&bins[keys[i] & 1023u], 1u);
    __syncthreads();

    scan_select<1024>(bins, wred, t, lane, wid, krB, prefB, 0, &sh_prefix, &sh_kr);
    __syncthreads();

    const unsigned T   = sh_prefix;              // exact 512th-largest key
    const unsigned kGT = KSEL - sh_kr;           // # keys strictly greater than T

    // ---- compact keys > T: warp exclusive scan + 1 atomic per warp ----
    {
        unsigned flags = 0, pcnt = 0;
        #pragma unroll
        for (int i = 0; i < 8; i++) {
            bool p = keys[i] > T;
            flags |= (unsigned)p << i;
            pcnt += p;
        }
        unsigned incl = pcnt;                    // inclusive warp scan
        #pragma unroll
        for (int d = 1; d < 32; d <<= 1) {
            unsigned v = __shfl_up_sync(0xFFFFFFFFu, incl, d);
            if (lane >= d) incl += v;
        }
        unsigned base = 0;
        if (lane == 31 && incl) base = atomicAdd(&sh_cnt, incl);
        base = __shfl_sync(0xFFFFFFFFu, base, 31);
        unsigned pos = base + incl - pcnt;
        #pragma unroll
        for (int i = 0; i < 8; i++)
            if ((flags >> i) & 1) skeys[0][pos++] = keys[i];
    }
    if ((unsigned)t >= kGT) skeys[0][t] = T;     // pad ties (disjoint indices)
    __syncthreads();

    // ---- V=4 register bitonic sort on 4 warps; everyone else leaves ----
    if (t >= SORT_T) return;

    uint4 vv = ((const uint4*)skeys[0])[t];      // elements 4t..4t+3
    unsigned v0 = vv.x, v1 = vv.y, v2 = vv.z, v3 = vv.w;
    int buf = 0;

    #define INREG(K2) { \
        bool up = (t & ((K2) >> 2)) == 0; \
        cswap(v0, v2, up); cswap(v1, v3, up); \
        cswap(v0, v1, up); cswap(v2, v3, up); }

    #define XSTAGE(K2, J) { \
        bool dir = ((t & ((K2) >> 2)) == 0) == ((t & ((J) >> 2)) == 0); \
        unsigned o0 = __shfl_xor_sync(0xFFFFFFFFu, v0, (J) >> 2); \
        unsigned o1 = __shfl_xor_sync(0xFFFFFFFFu, v1, (J) >> 2); \
        unsigned o2 = __shfl_xor_sync(0xFFFFFFFFu, v2, (J) >> 2); \
        unsigned o3 = __shfl_xor_sync(0xFFFFFFFFu, v3, (J) >> 2); \
        v0 = dir ? max(v0, o0) : min(v0, o0); \
        v1 = dir ? max(v1, o1) : min(v1, o1); \
        v2 = dir ? max(v2, o2) : min(v2, o2); \
        v3 = dir ? max(v3, o3) : min(v3, o3); }

    #define MSTAGE(K2, J) { \
        buf ^= 1; \
        ((uint4*)skeys[buf])[t] = make_uint4(v0, v1, v2, v3); \
        asm volatile("bar.sync 1, %0;" :: "r"(SORT_T) : "memory"); \
        uint4 o = ((const uint4*)skeys[buf])[t ^ ((J) >> 2)]; \
        bool dir = ((t & ((K2) >> 2)) == 0) == ((t & ((J) >> 2)) == 0); \
        v0 = dir ? max(v0, o.x) : min(v0, o.x); \
        v1 = dir ? max(v1, o.y) : min(v1, o.y); \
        v2 = dir ? max(v2, o.z) : min(v2, o.z); \
        v3 = dir ? max(v3, o.w) : min(v3, o.w); }

    cswap(v0, v1, true); cswap(v2, v3, false);       // k2 = 2
    INREG(4)                                          // k2 = 4
    XSTAGE(8, 4)   INREG(8)                           // k2 = 8
    XSTAGE(16, 8)  XSTAGE(16, 4)  INREG(16)           // k2 = 16
    XSTAGE(32, 16) XSTAGE(32, 8)  XSTAGE(32, 4)  INREG(32)
    XSTAGE(64, 32) XSTAGE(64, 16) XSTAGE(64, 8)  XSTAGE(64, 4)  INREG(64)
    XSTAGE(128, 64) XSTAGE(128, 32) XSTAGE(128, 16) XSTAGE(128, 8) XSTAGE(128, 4)
    INREG(128)
    MSTAGE(256, 128)
    XSTAGE(256, 64) XSTAGE(256, 32) XSTAGE(256, 16) XSTAGE(256, 8) XSTAGE(256, 4)
    INREG(256)
    MSTAGE(512, 256) MSTAGE(512, 128)
    XSTAGE(512, 64) XSTAGE(512, 32) XSTAGE(512, 16) XSTAGE(512, 8) XSTAGE(512, 4)
    INREG(512)

    float4 r;
    r.x = k2f(v0); r.y = k2f(v1); r.z = k2f(v2); r.w = k2f(v3);
    ((float4*)(out + row * (long long)KSEL))[t] = r;
}

extern "C" void kernel_launch(void* const* d_in, const int* in_sizes, int n_in,
                              void* d_out, int out_size) {
    const float* Q      = (const float*)d_in[0];
    const float* scores = (const float*)d_in[1];
    const float* W      = (const float*)d_in[2];
    const float* b      = (const float*)d_in[3];

    const int D = in_sizes[2];                        // 1024
    const long long BS = (long long)in_sizes[0] / D;  // B*S = 16384

    float* out  = (float*)d_out;
    float* outk = ((long long)out_size >= BS * KSEL + BS) ? out + BS * KSEL : nullptr;

    topk_kernel<<<(unsigned)BS, TPB>>>(scores, Q, W, b, out, outk, D);
}

// round 8
// speedup vs baseline: 2.0097x; 1.0859x over previous
#include <cuda_runtime.h>
#include <cuda_bf16.h>

// AdaptiveTokenSelector:
//   out[0 .. B*S*512)   = top-512 values per score row, sorted descending (f32)
//   out[B*S*512 .. +BS) = k_per_query = int(256 + 256*sigmoid(Q.W + b)) as f32
//
// One CTA (512 threads) per row, 8 register keys/thread:
//   - pass A: 12-bit histogram over keys >= MKEY (exact fallback loop with 0)
//   - early exit at any pass when crossing-bin count == needed count
//     (threshold = bin lower bound, exactly 512 survivors, no padding)
//   - passes B/C: 10-bit histograms over shrinking candidate sets
//   - scan_select: block suffix scan; crossing-bin loop gated to the one thread
//   - compaction: warp exclusive scan + 1 shared atomic per warp
//   - V=4 register bitonic sort on 128 threads (4 warps); other warps exit
//   - fused importance gate; __launch_bounds__(512,4) pins regs <= 32

#define TPB      512
#define ROWLEN   4096
#define KSEL     512
#define SORT_T   128
#define MKEY     0xBF000000u   /* f2k(0.5f): aligned to 12-bit bin boundary */

__device__ __forceinline__ unsigned f2k(float f) {
    unsigned u = __float_as_uint(f);
    return u ^ ((unsigned)((int)u >> 31) | 0x80000000u);
}

__device__ __forceinline__ float k2f(unsigned k) {
    unsigned u = (k & 0x80000000u) ? (k ^ 0x80000000u) : ~k;
    return __uint_as_float(u);
}

__device__ __forceinline__ void cswap(unsigned& a, unsigned& b, bool up) {
    unsigned hi = max(a, b), lo = min(a, b);
    a = up ? hi : lo;
    b = up ? lo : hi;
}

// Block suffix scan over NB bins; finds the bin holding the kr-th largest key.
// Writes prefix/kr-remaining/count-of-crossing-bin. wred[0] = total (after the
// caller's next __syncthreads). Crossing-bin inner loop runs on ONE thread.
template<int NB>
__device__ __forceinline__ void scan_select(const unsigned* __restrict__ bins,
                                            unsigned* wred,
                                            int t, unsigned lane, int wid,
                                            unsigned kr, unsigned prefix_base,
                                            int shift,
                                            unsigned* sh_prefix, unsigned* sh_kr,
                                            unsigned* sh_cbin) {
    constexpr int BPT = (NB == 4096) ? 8 : 4;
    constexpr int OWN = NB / BPT;
    constexpr int NW  = OWN / 32;
    unsigned c[BPT];
    unsigned sum = 0, s = 0;
    if (t < OWN) {
        const uint4* b4 = (const uint4*)(bins + t * BPT);
        uint4 v0 = b4[0];
        c[0] = v0.x; c[1] = v0.y; c[2] = v0.z; c[3] = v0.w;
        if (BPT == 8) {
            uint4 v1 = b4[1];
            c[4] = v1.x; c[5] = v1.y; c[6] = v1.z; c[7] = v1.w;
        }
        #pragma unroll
        for (int i = 0; i < BPT; i++) sum += c[i];
        s = sum;
        #pragma unroll
        for (int off = 1; off < 32; off <<= 1) {
            unsigned v = __shfl_down_sync(0xFFFFFFFFu, s, off);
            if (lane + off < 32) s += v;
        }
        if (lane == 0) wred[wid] = s;
    }
    __syncthreads();
    if (t < 32) {
        unsigned w = (lane < NW) ? wred[lane] : 0u;
        #pragma unroll
        for (int off = 1; off < NW; off <<= 1) {
            unsigned v = __shfl_down_sync(0xFFFFFFFFu, w, off);
            if (lane + off < NW) w += v;
        }
        if (lane < NW) wred[lane] = w;   // wred[0] = total
    }
    __syncthreads();
    if (t < OWN) {
        unsigned cum = (s - sum) + ((wid + 1 < NW) ? wred[wid + 1] : 0u);
        if (cum < kr && cum + sum >= kr) {     // this thread holds the crossing
            #pragma unroll
            for (int i = BPT - 1; i >= 0; i--) {
                unsigned nc = cum + c[i];
                if (cum < kr && nc >= kr) {
                    *sh_prefix = prefix_base | ((unsigned)(t * BPT + i) << shift);
                    *sh_kr = kr - cum;
                    *sh_cbin = c[i];
                }
                cum = nc;
            }
        }
    }
}

__global__ __launch_bounds__(TPB, 4) void topk_kernel(const float* __restrict__ scores,
                                                      const float* __restrict__ Q,
                                                      const float* __restrict__ W,
                                                      const float* __restrict__ bias,
                                                      float* __restrict__ out,
                                                      float* __restrict__ outk,
                                                      int D) {
    __shared__ __align__(16) unsigned bins[4096];
    __shared__ __align__(16) unsigned skeys[2][KSEL];
    __shared__ unsigned wred[16];
    __shared__ float red[TPB / 32];
    __shared__ unsigned sh_prefix, sh_kr, sh_cbin, sh_cnt;

    const int t = threadIdx.x;
    const unsigned lane = t & 31;
    const int wid = t >> 5;
    const long long row = blockIdx.x;
    const float4* src = (const float4*)(scores + row * (long long)ROWLEN);

    // ---- load 8 floats/thread, convert to sortable keys ----
    unsigned keys[8];
    {
        float4 a = src[t];
        float4 b = src[t + TPB];
        keys[0] = f2k(a.x); keys[1] = f2k(a.y); keys[2] = f2k(a.z); keys[3] = f2k(a.w);
        keys[4] = f2k(b.x); keys[5] = f2k(b.y); keys[6] = f2k(b.z); keys[7] = f2k(b.w);
    }

    // ---- fused importance gate: partial dot Q_row . W ----
    if (outk) {
        const float2* q2 = (const float2*)(Q + row * (long long)D);
        const float2* w2 = (const float2*)W;
        float s = 0.0f;
        for (int i = t; i < (D >> 1); i += TPB) {
            float2 q = q2[i], w = w2[i];
            s += q.x * w.x + q.y * w.y;
        }
        #pragma unroll
        for (int off = 16; off; off >>= 1) s += __shfl_down_sync(0xFFFFFFFFu, s, off);
        if (lane == 0) red[wid] = s;
    }

    if (t == 0) sh_cnt = 0;

    // ---- pass A: filtered 12-bit histogram; exact fallback loop ----
    unsigned filt = MKEY;
    for (;;) {
        {
            const uint4 z = make_uint4(0, 0, 0, 0);
            ((uint4*)bins)[t] = z;
            ((uint4*)bins)[t + TPB] = z;
        }
        __syncthreads();

        #pragma unroll
        for (int i = 0; i < 8; i++)
            if (keys[i] >= filt)
                atomicAdd(&bins[keys[i] >> 20], 1u);
        __syncthreads();

        if (filt == MKEY && outk && t == 0) {    // finish gate once
            float s = bias[0];
            #pragma unroll
            for (int w = 0; w < TPB / 32; w++) s += red[w];
            float imp = 1.0f / (1.0f + expf(-s));
            outk[row] = (float)(int)(256.0f + 256.0f * imp);
        }

        scan_select<4096>(bins, wred, t, lane, wid, KSEL, 0u, 20,
                          &sh_prefix, &sh_kr, &sh_cbin);
        __syncthreads();

        if (wred[0] >= KSEL || filt == 0u) break;
        filt = 0u;                               // retry unfiltered (exactness)
    }

    unsigned T, kGT;                             // compaction: keep keys > T
    {
        const unsigned prefA = sh_prefix;
        const unsigned krA   = sh_kr;
        if (sh_cbin == krA && prefA != 0u) {
            // whole crossing bin included: exactly 512 keys >= prefA
            T = prefA - 1u;
            kGT = KSEL;
        } else {
            __syncthreads();
            if (t < 256) ((uint4*)bins)[t] = make_uint4(0, 0, 0, 0);
            __syncthreads();

            // ---- pass B: 10-bit histogram over crossing-bin candidates ----
            unsigned flagsB = 0;
            #pragma unroll
            for (int i = 0; i < 8; i++) {
                bool c = ((keys[i] ^ prefA) >> 20) == 0;
                flagsB |= (unsigned)c << i;
                if (c) atomicAdd(&bins[(keys[i] >> 10) & 1023u], 1u);
            }
            __syncthreads();

            scan_select<1024>(bins, wred, t, lane, wid, krA, prefA, 10,
                              &sh_prefix, &sh_kr, &sh_cbin);
            __syncthreads();

            const unsigned prefB = sh_prefix;
            const unsigned krB   = sh_kr;
            if (sh_cbin == krB) {
                // whole crossing 10-bit bin included
                T = prefB - 1u;                  // prefB >= prefA > 0
                kGT = KSEL;
            } else {
                __syncthreads();
                if (t < 256) ((uint4*)bins)[t] = make_uint4(0, 0, 0, 0);
                __syncthreads();

                // ---- pass C: final 10 bits (candidates subset of flagsB) ----
                #pragma unroll
                for (int i = 0; i < 8; i++)
                    if (((flagsB >> i) & 1) && ((keys[i] ^ prefB) >> 10) == 0)
                        atomicAdd(&bins[keys[i] & 1023u], 1u);
                __syncthreads();

                scan_select<1024>(bins, wred, t, lane, wid, krB, prefB, 0,
                                  &sh_prefix, &sh_kr, &sh_cbin);
                __syncthreads();

                T = sh_prefix;                   // exact 512th-largest key
                kGT = KSEL - sh_kr;
            }
        }
    }

    // ---- compact keys > T: warp exclusive scan + 1 atomic per warp ----
    {
        unsigned flags = 0, pcnt = 0;
        #pragma unroll
        for (int i = 0; i < 8; i++) {
            bool p = keys[i] > T;
            flags |= (unsigned)p << i;
            pcnt += p;
        }
        unsigned incl = pcnt;                    // inclusive warp scan
        #pragma unroll
        for (int d = 1; d < 32; d <<= 1) {
            unsigned v = __shfl_up_sync(0xFFFFFFFFu, incl, d);
            if (lane >= d) incl += v;
        }
        unsigned base = 0;
        if (lane == 31 && incl) base = atomicAdd(&sh_cnt, incl);
        base = __shfl_sync(0xFFFFFFFFu, base, 31);
        unsigned pos = base + incl - pcnt;
        #pragma unroll
        for (int i = 0; i < 8; i++)
            if ((flags >> i) & 1) skeys[0][pos++] = keys[i];
    }
    if ((unsigned)t >= kGT) skeys[0][t] = T;     // pad ties (skipped if kGT=512)
    __syncthreads();

    // ---- V=4 register bitonic sort on 4 warps; everyone else leaves ----
    if (t >= SORT_T) return;

    uint4 vv = ((const uint4*)skeys[0])[t];      // elements 4t..4t+3
    unsigned v0 = vv.x, v1 = vv.y, v2 = vv.z, v3 = vv.w;
    int buf = 0;

    #define INREG(K2) { \
        bool up = (t & ((K2) >> 2)) == 0; \
        cswap(v0, v2, up); cswap(v1, v3, up); \
        cswap(v0, v1, up); cswap(v2, v3, up); }

    #define XSTAGE(K2, J) { \
        bool dir = ((t & ((K2) >> 2)) == 0) == ((t & ((J) >> 2)) == 0); \
        unsigned o0 = __shfl_xor_sync(0xFFFFFFFFu, v0, (J) >> 2); \
        unsigned o1 = __shfl_xor_sync(0xFFFFFFFFu, v1, (J) >> 2); \
        unsigned o2 = __shfl_xor_sync(0xFFFFFFFFu, v2, (J) >> 2); \
        unsigned o3 = __shfl_xor_sync(0xFFFFFFFFu, v3, (J) >> 2); \
        v0 = dir ? max(v0, o0) : min(v0, o0); \
        v1 = dir ? max(v1, o1) : min(v1, o1); \
        v2 = dir ? max(v2, o2) : min(v2, o2); \
        v3 = dir ? max(v3, o3) : min(v3, o3); }

    #define MSTAGE(K2, J) { \
        buf ^= 1; \
        ((uint4*)skeys[buf])[t] = make_uint4(v0, v1, v2, v3); \
        asm volatile("bar.sync 1, %0;" :: "r"(SORT_T) : "memory"); \
        uint4 o = ((const uint4*)skeys[buf])[t ^ ((J) >> 2)]; \
        bool dir = ((t & ((K2) >> 2)) == 0) == ((t & ((J) >> 2)) == 0); \
        v0 = dir ? max(v0, o.x) : min(v0, o.x); \
        v1 = dir ? max(v1, o.y) : min(v1, o.y); \
        v2 = dir ? max(v2, o.z) : min(v2, o.z); \
        v3 = dir ? max(v3, o.w) : min(v3, o.w); }

    cswap(v0, v1, true); cswap(v2, v3, false);       // k2 = 2
    INREG(4)                                          // k2 = 4
    XSTAGE(8, 4)   INREG(8)                           // k2 = 8
    XSTAGE(16, 8)  XSTAGE(16, 4)  INREG(16)           // k2 = 16
    XSTAGE(32, 16) XSTAGE(32, 8)  XSTAGE(32, 4)  INREG(32)
    XSTAGE(64, 32) XSTAGE(64, 16) XSTAGE(64, 8)  XSTAGE(64, 4)  INREG(64)
    XSTAGE(128, 64) XSTAGE(128, 32) XSTAGE(128, 16) XSTAGE(128, 8) XSTAGE(128, 4)
    INREG(128)
    MSTAGE(256, 128)
    XSTAGE(256, 64) XSTAGE(256, 32) XSTAGE(256, 16) XSTAGE(256, 8) XSTAGE(256, 4)
    INREG(256)
    MSTAGE(512, 256) MSTAGE(512, 128)
    XSTAGE(512, 64) XSTAGE(512, 32) XSTAGE(512, 16) XSTAGE(512, 8) XSTAGE(512, 4)
    INREG(512)

    float4 r;
    r.x = k2f(v0); r.y = k2f(v1); r.z = k2f(v2); r.w = k2f(v3);
    ((float4*)(out + row * (long long)KSEL))[t] = r;
}

extern "C" void kernel_launch(void* const* d_in, const int* in_sizes, int n_in,
                              void* d_out, int out_size) {
    const float* Q      = (const float*)d_in[0];
    const float* scores = (const float*)d_in[1];
    const float* W      = (const float*)d_in[2];
    const float* b      = (const float*)d_in[3];

    const int D = in_sizes[2];                        // 1024
    const long long BS = (long long)in_sizes[0] / D;  // B*S = 16384

    float* out  = (float*)d_out;
    float* outk = ((long long)out_size >= BS * KSEL + BS) ? out + BS * KSEL : nullptr;

    topk_kernel<<<(unsigned)BS, TPB>>>(scores, Q, W, b, out, outk, D);
}